// round 8
// baseline (speedup 1.0000x reference)
#include <cuda_runtime.h>
#include <cuda_bf16.h>
#include <stdint.h>
#include <math.h>

#define BN 16384
#define DN 256
#define PN 512
#define CN 20
#define NSEG 8
#define SEGL (PN / NSEG)   // 64

// ---------------------------------------------------------------------------
// Device-global scratch (no allocations allowed)
// ---------------------------------------------------------------------------
__device__ float g_s[(size_t)PN * BN];   // s[k][b], 32 MB
__device__ float g_U[PN * CN];
__device__ float g_A[PN];                // alphap*exp(-g2*0.5*||W||^2)
__device__ float g_g2l[PN];              // g2 * log2(e)
__device__ float g_hx[BN];               // 0.5*||x_b||^2
__device__ float g_segT[NSEG][CN][BN];   // partial products of a = U*s+1-s
__device__ float g_segD[NSEG][BN];       // partial products of 1-s

__device__ __nv_bfloat16 g_Xh[(size_t)BN * DN];
__device__ __nv_bfloat16 g_Xl[(size_t)BN * DN];
__device__ __nv_bfloat16 g_Wh[PN * DN];

#define SW128(off) ((off) ^ (((off) >> 3) & 0x70))

// ---------------------------------------------------------------------------
// mma.sync / ldmatrix / f32x2 / cp.async wrappers (base sm_103 features)
// ---------------------------------------------------------------------------
__device__ __forceinline__ void ldsm_x4(uint32_t& r0, uint32_t& r1, uint32_t& r2,
                                        uint32_t& r3, uint32_t addr) {
    asm volatile("ldmatrix.sync.aligned.m8n8.x4.shared.b16 {%0,%1,%2,%3}, [%4];"
                 : "=r"(r0), "=r"(r1), "=r"(r2), "=r"(r3) : "r"(addr));
}
__device__ __forceinline__ void mma16816(float* d, const uint32_t* a, const uint32_t* b) {
    asm volatile("mma.sync.aligned.m16n8k16.row.col.f32.bf16.bf16.f32 "
                 "{%0,%1,%2,%3}, {%4,%5,%6,%7}, {%8,%9}, {%0,%1,%2,%3};"
                 : "+f"(d[0]), "+f"(d[1]), "+f"(d[2]), "+f"(d[3])
                 : "r"(a[0]), "r"(a[1]), "r"(a[2]), "r"(a[3]), "r"(b[0]), "r"(b[1]));
}
__device__ __forceinline__ uint32_t smem_u32(const void* p) {
    uint32_t a;
    asm("{ .reg .u64 t; cvta.to.shared.u64 t, %1; cvt.u32.u64 %0, t; }" : "=r"(a) : "l"(p));
    return a;
}
__device__ __forceinline__ void cp16(uint32_t dst, const void* src) {
    asm volatile("cp.async.cg.shared.global [%0], [%1], 16;" :: "r"(dst), "l"(src));
}
#define CP_COMMIT() asm volatile("cp.async.commit_group;" ::: "memory")
#define CP_WAIT(n)  asm volatile("cp.async.wait_group %0;" :: "n"(n) : "memory")

__device__ __forceinline__ uint64_t pack2(float x) {
    uint64_t r;
    asm("mov.b64 %0, {%1, %1};" : "=l"(r) : "f"(x));
    return r;
}
__device__ __forceinline__ uint64_t pack2f(float lo, float hi) {
    uint64_t r;
    asm("mov.b64 %0, {%1, %2};" : "=l"(r) : "f"(lo), "f"(hi));
    return r;
}
__device__ __forceinline__ uint64_t fma2(uint64_t a, uint64_t b, uint64_t c) {
    uint64_t d;
    asm("fma.rn.f32x2 %0, %1, %2, %3;" : "=l"(d) : "l"(a), "l"(b), "l"(c));
    return d;
}
__device__ __forceinline__ uint64_t add2(uint64_t a, uint64_t b) {
    uint64_t d;
    asm("add.rn.f32x2 %0, %1, %2;" : "=l"(d) : "l"(a), "l"(b));
    return d;
}
__device__ __forceinline__ uint64_t mul2(uint64_t a, uint64_t b) {
    uint64_t d;
    asm("mul.rn.f32x2 %0, %1, %2;" : "=l"(d) : "l"(a), "l"(b));
    return d;
}
__device__ __forceinline__ void unpack2(float& lo, float& hi, uint64_t v) {
    asm("mov.b64 {%0, %1}, %2;" : "=f"(lo), "=f"(hi) : "l"(v));
}

// ---------------------------------------------------------------------------
// Prep per-prototype: ||W||^2, U row, A, g2*log2e, W -> bf16 (hi only)
// ---------------------------------------------------------------------------
__global__ void prep_proto_kernel(const float* __restrict__ W,
                                  const float* __restrict__ BETA,
                                  const float* __restrict__ alpha,
                                  const float* __restrict__ gamma) {
    int k = blockIdx.x;
    int lane = threadIdx.x;

    float sum = 0.f;
    const float4* wr = (const float4*)(W + k * DN);
#pragma unroll
    for (int i = 0; i < 2; i++) {
        float4 v = wr[lane + i * 32];
        sum += v.x * v.x + v.y * v.y + v.z * v.z + v.w * v.w;
        int base = k * DN + (lane + i * 32) * 4;
        *(__nv_bfloat162*)(g_Wh + base) =
            __nv_bfloat162(__float2bfloat16(v.x), __float2bfloat16(v.y));
        *(__nv_bfloat162*)(g_Wh + base + 2) =
            __nv_bfloat162(__float2bfloat16(v.z), __float2bfloat16(v.w));
    }
#pragma unroll
    for (int o = 16; o; o >>= 1) sum += __shfl_xor_sync(0xffffffffu, sum, o);

    float b2 = 0.f;
    if (lane < CN) {
        float bb = BETA[k * CN + lane];
        b2 = bb * bb;
    }
    float bsum = b2;
#pragma unroll
    for (int o = 16; o; o >>= 1) bsum += __shfl_xor_sync(0xffffffffu, bsum, o);
    if (lane < CN) g_U[k * CN + lane] = b2 / bsum;

    if (lane == 0) {
        float g  = gamma[k];
        float g2 = g * g;
        float ap = 0.99f / (1.f + expf(-alpha[k]));
        g_g2l[k] = g2 * 1.4426950408889634f;
        g_A[k]   = ap * expf(-g2 * 0.5f * sum);
    }
}

// ---------------------------------------------------------------------------
// Prep per-batch: 0.5*||x||^2 and X -> bf16 hi/lo. One warp per row.
// ---------------------------------------------------------------------------
__global__ void prep_x_kernel(const float* __restrict__ X) {
    int row  = blockIdx.x * 8 + (threadIdx.x >> 5);
    int lane = threadIdx.x & 31;
    float sum = 0.f;
    const float4* xr = (const float4*)(X + (size_t)row * DN);
#pragma unroll
    for (int i = 0; i < 2; i++) {
        float4 v = xr[lane + i * 32];
        sum += v.x * v.x + v.y * v.y + v.z * v.z + v.w * v.w;
        size_t base = (size_t)row * DN + (lane + i * 32) * 4;
        __nv_bfloat16 h0 = __float2bfloat16(v.x);
        __nv_bfloat16 h1 = __float2bfloat16(v.y);
        __nv_bfloat16 h2 = __float2bfloat16(v.z);
        __nv_bfloat16 h3 = __float2bfloat16(v.w);
        __nv_bfloat16 l0 = __float2bfloat16(v.x - __bfloat162float(h0));
        __nv_bfloat16 l1 = __float2bfloat16(v.y - __bfloat162float(h1));
        __nv_bfloat16 l2 = __float2bfloat16(v.z - __bfloat162float(h2));
        __nv_bfloat16 l3 = __float2bfloat16(v.w - __bfloat162float(h3));
        *(__nv_bfloat162*)(g_Xh + base)     = __nv_bfloat162(h0, h1);
        *(__nv_bfloat162*)(g_Xh + base + 2) = __nv_bfloat162(h2, h3);
        *(__nv_bfloat162*)(g_Xl + base)     = __nv_bfloat162(l0, l1);
        *(__nv_bfloat162*)(g_Xl + base + 2) = __nv_bfloat162(l2, l3);
    }
#pragma unroll
    for (int o = 16; o; o >>= 1) sum += __shfl_xor_sync(0xffffffffu, sum, o);
    if (lane == 0) g_hx[row] = 0.5f * sum;
}

// ---------------------------------------------------------------------------
// HMMA GEMM: D[b,p] = (Xh+Xl).Wh  (K=512 effective), cp.async pipelined.
// Block 128b x 256p, 512 threads; warp tile 64x32.
// ---------------------------------------------------------------------------
#define SM_A0 0
#define SM_A1 16384
#define SM_W0 32768
#define SM_W1 65536
#define SMEM_TOTAL 98304   // 96 KB
#define STAGE_PITCH 132    // floats

__global__ void __launch_bounds__(512, 1)
gemm_hmma_kernel() {
    extern __shared__ char smem[];
    const uint32_t smem_base = smem_u32(smem);
    const int t    = threadIdx.x;
    const int wid  = t >> 5;
    const int lane = t & 31;
    const int wrow = wid >> 3;
    const int wcol = wid & 7;
    const int b0   = blockIdx.x * 128;
    const int p0   = blockIdx.y * 256;

    const int abase[2] = {SM_A0, SM_A1};
    const int wbase[2] = {SM_W0, SM_W1};

    float acc[4][4][4];
#pragma unroll
    for (int mt = 0; mt < 4; mt++)
#pragma unroll
        for (int nt = 0; nt < 4; nt++)
#pragma unroll
            for (int v = 0; v < 4; v++) acc[mt][nt][v] = 0.f;

    auto load_a = [&](int part, int koff, int buf) {
        const __nv_bfloat16* As = part ? g_Xl : g_Xh;
#pragma unroll
        for (int i = 0; i < 2; i++) {
            int idx = t + i * 512;
            int row = idx >> 3, v = idx & 7;
            cp16(smem_base + abase[buf] + SW128(row * 128 + v * 16),
                 As + (size_t)(b0 + row) * DN + koff + v * 8);
        }
    };
    auto load_w = [&](int koff, int buf) {
#pragma unroll
        for (int i = 0; i < 4; i++) {
            int idx = t + i * 512;
            int row = idx >> 3, v = idx & 7;
            cp16(smem_base + wbase[buf] + SW128(row * 128 + v * 16),
                 g_Wh + (size_t)(p0 + row) * DN + koff + v * 8);
        }
    };

    load_a(0, 0, 0);
    load_w(0, 0);
    CP_COMMIT();

    const int lm = lane & 15;
    const int lq = lane >> 4;

    // virtual chunk c: k = c>>1, part = c&1 (0:Xh, 1:Xl). Wh[k] reused.
    for (int c = 0; c < 8; c++) {
        int ab = c & 1;
        int wb = (c >> 1) & 1;
        if (c < 7) {
            int nc = c + 1;
            load_a(nc & 1, (nc >> 1) * 64, ab ^ 1);
            if (!(nc & 1)) load_w((nc >> 1) * 64, (nc >> 1) & 1);
            CP_COMMIT();
            CP_WAIT(1);
        } else {
            CP_WAIT(0);
        }
        __syncthreads();

        uint32_t Ab = smem_base + abase[ab];
        uint32_t Bb = smem_base + wbase[wb];
#pragma unroll
        for (int ks = 0; ks < 4; ks++) {
            uint32_t a[4][4];
#pragma unroll
            for (int mt = 0; mt < 4; mt++)
                ldsm_x4(a[mt][0], a[mt][1], a[mt][2], a[mt][3],
                        Ab + SW128((wrow * 64 + mt * 16 + lm) * 128 + ks * 32 + lq * 16));
            uint32_t br[2][4];
#pragma unroll
            for (int bt = 0; bt < 2; bt++)
                ldsm_x4(br[bt][0], br[bt][1], br[bt][2], br[bt][3],
                        Bb + SW128((wcol * 32 + bt * 16 + lm) * 128 + ks * 32 + lq * 16));
#pragma unroll
            for (int mt = 0; mt < 4; mt++) {
#pragma unroll
                for (int bt = 0; bt < 2; bt++) {
                    uint32_t f0[2] = {br[bt][0], br[bt][2]};
                    uint32_t f1[2] = {br[bt][1], br[bt][3]};
                    mma16816(acc[mt][bt * 2 + 0], a[mt], f0);
                    mma16816(acc[mt][bt * 2 + 1], a[mt], f1);
                }
            }
        }
        __syncthreads();
    }

    // --- Epilogue (packed f32x2 exp2 over adjacent-p pairs) ---
    float hx0[4], hx1[4];
#pragma unroll
    for (int mt = 0; mt < 4; mt++) {
        hx0[mt] = g_hx[b0 + wrow * 64 + mt * 16 + (lane >> 2)];
        hx1[mt] = g_hx[b0 + wrow * 64 + mt * 16 + (lane >> 2) + 8];
    }
    uint64_t g2l2[4], Ap2[4];
#pragma unroll
    for (int nt = 0; nt < 4; nt++) {
        int p = p0 + wcol * 32 + nt * 8 + (lane & 3) * 2;
        g2l2[nt] = *(const uint64_t*)(&g_g2l[p]);
        Ap2[nt]  = *(const uint64_t*)(&g_A[p]);
    }
    const uint64_t MAG2  = pack2(12582912.f);
    const uint64_t NEG12 = pack2(-1.f);
    const uint64_t P5 = pack2(1.3333558146e-3f);
    const uint64_t P4 = pack2(9.6181291076e-3f);
    const uint64_t P3 = pack2(5.5504108664e-2f);
    const uint64_t P2 = pack2(2.4022650696e-1f);
    const uint64_t P1 = pack2(6.9314718056e-1f);
    const uint64_t P0 = pack2(1.0f);

    float* stage = (float*)smem;

#pragma unroll
    for (int half = 0; half < 2; half++) {
        if ((wcol >> 2) == half) {
            int prow0 = (wcol & 3) * 32;
#pragma unroll
            for (int mt = 0; mt < 4; mt++)
#pragma unroll
                for (int pv = 0; pv < 2; pv++) {
                    uint64_t nhx2 = pack2(pv ? -hx1[mt] : -hx0[mt]);
                    int bc = wrow * 64 + mt * 16 + (lane >> 2) + pv * 8;
#pragma unroll
                    for (int nt = 0; nt < 4; nt++) {
                        uint64_t acc2 = pack2f(acc[mt][nt][2 * pv], acc[mt][nt][2 * pv + 1]);
                        uint64_t tt = mul2(add2(acc2, nhx2), g2l2[nt]);
                        uint64_t tr = add2(tt, MAG2);
                        uint64_t fn = fma2(MAG2, NEG12, tr);   // tr - MAG
                        uint64_t f  = fma2(fn, NEG12, tt);     // tt - fn
                        uint64_t pl = fma2(P5, f, P4);
                        pl = fma2(pl, f, P3);
                        pl = fma2(pl, f, P2);
                        pl = fma2(pl, f, P1);
                        pl = fma2(pl, f, P0);
                        pl = mul2(pl, Ap2[nt]);
                        float pl0, pl1, tr0, tr1;
                        unpack2(pl0, pl1, pl);
                        unpack2(tr0, tr1, tr);
                        float ex0 = __int_as_float(__float_as_int(pl0) + (__float_as_int(tr0) << 23));
                        float ex1 = __int_as_float(__float_as_int(pl1) + (__float_as_int(tr1) << 23));
                        int pr = prow0 + nt * 8 + (lane & 3) * 2;
                        stage[(pr + 0) * STAGE_PITCH + bc] = ex0;
                        stage[(pr + 1) * STAGE_PITCH + bc] = ex1;
                    }
                }
        }
        __syncthreads();
#pragma unroll
        for (int i = 0; i < 8; i++) {
            int idx = t + i * 512;
            int row = idx >> 5;
            int c4  = idx & 31;
            float4 val = *(const float4*)(stage + row * STAGE_PITCH + c4 * 4);
            *(float4*)(&g_s[(size_t)(p0 + half * 128 + row) * BN + b0 + c4 * 4]) = val;
        }
        __syncthreads();
    }
}

// ---------------------------------------------------------------------------
// Scan segments: PURE PRODUCTS. T[c] = prod_k (U[k][c]*s + 1 - s), D = prod(1-s)
// (identity: mc + mn evolves multiplicatively; mc = T - D at the end)
// ---------------------------------------------------------------------------
__global__ void __launch_bounds__(256) scan_seg_kernel() {
    __shared__ __align__(16) float Us[SEGL][CN];
    const int seg = blockIdx.y;
    const int k0  = seg * SEGL;
    for (int i = threadIdx.x; i < SEGL * CN; i += 256)
        ((float*)Us)[i] = g_U[k0 * CN + i];
    __syncthreads();

    const int b = blockIdx.x * 256 + threadIdx.x;

    uint64_t T2[10];
    const uint64_t ONE2 = 0x3F8000003F800000ULL;
#pragma unroll
    for (int i = 0; i < 10; i++) T2[i] = ONE2;
    float D = 1.f;

    float cur[8], nxt[8];
#pragma unroll
    for (int i = 0; i < 8; i++) cur[i] = g_s[(size_t)(k0 + i) * BN + b];

    for (int kk = 0; kk < SEGL; kk += 8) {
        if (kk + 8 < SEGL) {
#pragma unroll
            for (int i = 0; i < 8; i++) nxt[i] = g_s[(size_t)(k0 + kk + 8 + i) * BN + b];
        }
#pragma unroll
        for (int i = 0; i < 8; i++) {
            float sk  = cur[i];
            float mn1 = 1.f - sk;
            uint64_t ss2 = pack2(sk);
            uint64_t mn2 = pack2(mn1);
            const ulonglong2* u2 = (const ulonglong2*)(&Us[kk + i][0]);
#pragma unroll
            for (int j = 0; j < 5; j++) {
                ulonglong2 up = u2[j];
                T2[j * 2 + 0] = mul2(T2[j * 2 + 0], fma2(up.x, ss2, mn2));
                T2[j * 2 + 1] = mul2(T2[j * 2 + 1], fma2(up.y, ss2, mn2));
            }
            D *= mn1;
        }
#pragma unroll
        for (int i = 0; i < 8; i++) cur[i] = nxt[i];
    }

#pragma unroll
    for (int i = 0; i < 10; i++) {
        float lo, hi;
        unpack2(lo, hi, T2[i]);
        g_segT[seg][i * 2 + 0][b] = lo;
        g_segT[seg][i * 2 + 1][b] = hi;
    }
    g_segD[seg][b] = D;
}

// ---------------------------------------------------------------------------
// Combine: multiply segment partials, mc = T - D, normalize.
// 4 threads per b, 5 classes each.
// ---------------------------------------------------------------------------
__global__ void __launch_bounds__(256) combine_kernel(float* __restrict__ out) {
    const int gt = blockIdx.x * 256 + threadIdx.x;
    const int b  = gt >> 2;
    const int cg = gt & 3;

    float T[5], D = 1.f;
#pragma unroll
    for (int j = 0; j < 5; j++) T[j] = 1.f;

#pragma unroll
    for (int s = 0; s < NSEG; s++) {
#pragma unroll
        for (int j = 0; j < 5; j++) T[j] *= g_segT[s][cg * 5 + j][b];
        D *= g_segD[s][b];
    }

    float Ts = 0.f;
#pragma unroll
    for (int j = 0; j < 5; j++) Ts += T[j];
    Ts += __shfl_xor_sync(0xffffffffu, Ts, 1);
    Ts += __shfl_xor_sync(0xffffffffu, Ts, 2);
    float K = Ts - 19.f * D;
    float r = 1.f / K;

#pragma unroll
    for (int j = 0; j < 5; j++) out[b * (CN + 1) + cg * 5 + j] = (T[j] - D) * r;
    if (cg == 3) out[b * (CN + 1) + CN] = D * r;
}

// ---------------------------------------------------------------------------
extern "C" void kernel_launch(void* const* d_in, const int* in_sizes, int n_in,
                              void* d_out, int out_size) {
    const float* X     = (const float*)d_in[0];
    const float* W     = (const float*)d_in[1];
    const float* BETA  = (const float*)d_in[2];
    const float* alpha = (const float*)d_in[3];
    const float* gamma = (const float*)d_in[4];
    float* out = (float*)d_out;

    cudaFuncSetAttribute(gemm_hmma_kernel,
                         cudaFuncAttributeMaxDynamicSharedMemorySize, SMEM_TOTAL);

    prep_proto_kernel<<<PN, 32>>>(W, BETA, alpha, gamma);
    prep_x_kernel<<<BN / 8, 256>>>(X);

    dim3 ggrid(BN / 128, PN / 256);
    gemm_hmma_kernel<<<ggrid, 512, SMEM_TOTAL>>>();

    dim3 sgrid(BN / 256, NSEG);
    scan_seg_kernel<<<sgrid, 256>>>();

    combine_kernel<<<BN * 4 / 256, 256>>>(out);
}

// round 9
// speedup vs baseline: 1.7732x; 1.7732x over previous
#include <cuda_runtime.h>
#include <cuda_bf16.h>
#include <stdint.h>
#include <math.h>

#define BN 16384
#define DN 256
#define PN 512
#define CN 20
#define NSEG 8
#define SEGL (PN / NSEG)   // 64

// ---------------------------------------------------------------------------
// Device-global scratch (no allocations allowed)
// ---------------------------------------------------------------------------
__device__ float g_s[(size_t)PN * BN];   // s[k][b], 32 MB
__device__ float g_U[PN * CN];
__device__ float g_A[PN];                // alphap*exp(-g2*0.5*||W||^2)
__device__ float g_g2l[PN];              // g2 * log2(e)
__device__ float g_hx[BN];               // 0.5*||x_b||^2
__device__ float g_segT[NSEG][CN][BN];   // partial products of a = U*s+1-s
__device__ float g_segD[NSEG][BN];       // partial products of 1-s

__device__ __nv_bfloat16 g_Xh[(size_t)BN * DN];
__device__ __nv_bfloat16 g_Wh[PN * DN];

#define SW128(off) ((off) ^ (((off) >> 3) & 0x70))

// ---------------------------------------------------------------------------
// mma.sync / ldmatrix / f32x2 wrappers (base sm_103 features)
// ---------------------------------------------------------------------------
__device__ __forceinline__ void ldsm_x4(uint32_t& r0, uint32_t& r1, uint32_t& r2,
                                        uint32_t& r3, uint32_t addr) {
    asm volatile("ldmatrix.sync.aligned.m8n8.x4.shared.b16 {%0,%1,%2,%3}, [%4];"
                 : "=r"(r0), "=r"(r1), "=r"(r2), "=r"(r3) : "r"(addr));
}
__device__ __forceinline__ void mma16816(float* d, const uint32_t* a, const uint32_t* b) {
    asm volatile("mma.sync.aligned.m16n8k16.row.col.f32.bf16.bf16.f32 "
                 "{%0,%1,%2,%3}, {%4,%5,%6,%7}, {%8,%9}, {%0,%1,%2,%3};"
                 : "+f"(d[0]), "+f"(d[1]), "+f"(d[2]), "+f"(d[3])
                 : "r"(a[0]), "r"(a[1]), "r"(a[2]), "r"(a[3]), "r"(b[0]), "r"(b[1]));
}
__device__ __forceinline__ uint32_t smem_u32(const void* p) {
    uint32_t a;
    asm("{ .reg .u64 t; cvta.to.shared.u64 t, %1; cvt.u32.u64 %0, t; }" : "=r"(a) : "l"(p));
    return a;
}
__device__ __forceinline__ uint64_t pack2(float x) {
    uint64_t r;
    asm("mov.b64 %0, {%1, %1};" : "=l"(r) : "f"(x));
    return r;
}
__device__ __forceinline__ uint64_t fma2(uint64_t a, uint64_t b, uint64_t c) {
    uint64_t d;
    asm("fma.rn.f32x2 %0, %1, %2, %3;" : "=l"(d) : "l"(a), "l"(b), "l"(c));
    return d;
}
__device__ __forceinline__ uint64_t mul2(uint64_t a, uint64_t b) {
    uint64_t d;
    asm("mul.rn.f32x2 %0, %1, %2;" : "=l"(d) : "l"(a), "l"(b));
    return d;
}
__device__ __forceinline__ void unpack2(float& lo, float& hi, uint64_t v) {
    asm("mov.b64 {%0, %1}, %2;" : "=f"(lo), "=f"(hi) : "l"(v));
}

// ---------------------------------------------------------------------------
// Prep per-prototype: ||W||^2, U row, A, g2*log2e, W -> bf16
// ---------------------------------------------------------------------------
__global__ void prep_proto_kernel(const float* __restrict__ W,
                                  const float* __restrict__ BETA,
                                  const float* __restrict__ alpha,
                                  const float* __restrict__ gamma) {
    int k = blockIdx.x;
    int lane = threadIdx.x;

    float sum = 0.f;
    const float4* wr = (const float4*)(W + k * DN);
#pragma unroll
    for (int i = 0; i < 2; i++) {
        float4 v = wr[lane + i * 32];
        sum += v.x * v.x + v.y * v.y + v.z * v.z + v.w * v.w;
        int base = k * DN + (lane + i * 32) * 4;
        *(__nv_bfloat162*)(g_Wh + base) =
            __nv_bfloat162(__float2bfloat16(v.x), __float2bfloat16(v.y));
        *(__nv_bfloat162*)(g_Wh + base + 2) =
            __nv_bfloat162(__float2bfloat16(v.z), __float2bfloat16(v.w));
    }
#pragma unroll
    for (int o = 16; o; o >>= 1) sum += __shfl_xor_sync(0xffffffffu, sum, o);

    float b2 = 0.f;
    if (lane < CN) {
        float bb = BETA[k * CN + lane];
        b2 = bb * bb;
    }
    float bsum = b2;
#pragma unroll
    for (int o = 16; o; o >>= 1) bsum += __shfl_xor_sync(0xffffffffu, bsum, o);
    if (lane < CN) g_U[k * CN + lane] = b2 / bsum;

    if (lane == 0) {
        float g  = gamma[k];
        float g2 = g * g;
        float ap = 0.99f / (1.f + expf(-alpha[k]));
        g_g2l[k] = g2 * 1.4426950408889634f;
        g_A[k]   = ap * expf(-g2 * 0.5f * sum);
    }
}

// ---------------------------------------------------------------------------
// Prep per-batch: 0.5*||x||^2 and X -> bf16. One warp per row.
// ---------------------------------------------------------------------------
__global__ void prep_x_kernel(const float* __restrict__ X) {
    int row  = blockIdx.x * 8 + (threadIdx.x >> 5);
    int lane = threadIdx.x & 31;
    float sum = 0.f;
    const float4* xr = (const float4*)(X + (size_t)row * DN);
#pragma unroll
    for (int i = 0; i < 2; i++) {
        float4 v = xr[lane + i * 32];
        sum += v.x * v.x + v.y * v.y + v.z * v.z + v.w * v.w;
        size_t base = (size_t)row * DN + (lane + i * 32) * 4;
        *(__nv_bfloat162*)(g_Xh + base) =
            __nv_bfloat162(__float2bfloat16(v.x), __float2bfloat16(v.y));
        *(__nv_bfloat162*)(g_Xh + base + 2) =
            __nv_bfloat162(__float2bfloat16(v.z), __float2bfloat16(v.w));
    }
#pragma unroll
    for (int o = 16; o; o >>= 1) sum += __shfl_xor_sync(0xffffffffu, sum, o);
    if (lane == 0) g_hx[row] = 0.5f * sum;
}

// ---------------------------------------------------------------------------
// HMMA GEMM: D[b,p] = Xh.Wh (K=256, single bf16 pass).
// Block 128b x 256p, 512 threads; warp tile 64x32. 4 chunks double-buffered.
// Epilogue: s = A * 2^((dot - hx) * g2l) via FFMA exp2; smem transpose stage;
// coalesced g_s[p][b] writes.
// ---------------------------------------------------------------------------
#define SM_A0 0
#define SM_A1 16384
#define SM_W0 32768
#define SM_W1 65536
#define SMEM_TOTAL 98304   // 96 KB
#define STAGE_PITCH 132    // floats

__global__ void __launch_bounds__(512, 1)
gemm_hmma_kernel() {
    extern __shared__ char smem[];
    const uint32_t smem_base = smem_u32(smem);
    const int t    = threadIdx.x;
    const int wid  = t >> 5;
    const int lane = t & 31;
    const int wrow = wid >> 3;     // 0..1  -> 64 b rows each
    const int wcol = wid & 7;      // 0..7  -> 32 p cols each
    const int b0   = blockIdx.x * 128;
    const int p0   = blockIdx.y * 256;

    const int abase[2] = {SM_A0, SM_A1};
    const int wbase[2] = {SM_W0, SM_W1};

    float acc[4][4][4];
#pragma unroll
    for (int mt = 0; mt < 4; mt++)
#pragma unroll
        for (int nt = 0; nt < 4; nt++)
#pragma unroll
            for (int v = 0; v < 4; v++) acc[mt][nt][v] = 0.f;

    auto load_chunk = [&](int koff, int buf) {
#pragma unroll
        for (int i = 0; i < 2; i++) {
            int idx = t + i * 512;
            int row = idx >> 3, v = idx & 7;
            uint4 val = *(const uint4*)(g_Xh + (size_t)(b0 + row) * DN + koff + v * 8);
            *(uint4*)(smem + abase[buf] + SW128(row * 128 + v * 16)) = val;
        }
#pragma unroll
        for (int i = 0; i < 4; i++) {
            int idx = t + i * 512;
            int row = idx >> 3, v = idx & 7;
            uint4 val = *(const uint4*)(g_Wh + (size_t)(p0 + row) * DN + koff + v * 8);
            *(uint4*)(smem + wbase[buf] + SW128(row * 128 + v * 16)) = val;
        }
    };

    load_chunk(0, 0);
    __syncthreads();

    const int lm = lane & 15;
    const int lq = lane >> 4;

    for (int c = 0; c < 4; c++) {
        int cur = c & 1;
        if (c < 3) load_chunk((c + 1) * 64, cur ^ 1);

        uint32_t Ab = smem_base + abase[cur];
        uint32_t Bb = smem_base + wbase[cur];
#pragma unroll
        for (int ks = 0; ks < 4; ks++) {
            uint32_t a[4][4];
#pragma unroll
            for (int mt = 0; mt < 4; mt++)
                ldsm_x4(a[mt][0], a[mt][1], a[mt][2], a[mt][3],
                        Ab + SW128((wrow * 64 + mt * 16 + lm) * 128 + ks * 32 + lq * 16));
            uint32_t br[2][4];
#pragma unroll
            for (int bt = 0; bt < 2; bt++)
                ldsm_x4(br[bt][0], br[bt][1], br[bt][2], br[bt][3],
                        Bb + SW128((wcol * 32 + bt * 16 + lm) * 128 + ks * 32 + lq * 16));
#pragma unroll
            for (int mt = 0; mt < 4; mt++) {
#pragma unroll
                for (int bt = 0; bt < 2; bt++) {
                    uint32_t f0[2] = {br[bt][0], br[bt][2]};
                    uint32_t f1[2] = {br[bt][1], br[bt][3]};
                    mma16816(acc[mt][bt * 2 + 0], a[mt], f0);
                    mma16816(acc[mt][bt * 2 + 1], a[mt], f1);
                }
            }
        }
        __syncthreads();
    }

    // --- Epilogue (scalar, register-safe) ---
    float hx0[4], hx1[4];
#pragma unroll
    for (int mt = 0; mt < 4; mt++) {
        hx0[mt] = g_hx[b0 + wrow * 64 + mt * 16 + (lane >> 2)];
        hx1[mt] = g_hx[b0 + wrow * 64 + mt * 16 + (lane >> 2) + 8];
    }
    float g2l[4][2], Ap[4][2];
#pragma unroll
    for (int nt = 0; nt < 4; nt++) {
        int p = p0 + wcol * 32 + nt * 8 + (lane & 3) * 2;
        g2l[nt][0] = g_g2l[p];
        g2l[nt][1] = g_g2l[p + 1];
        Ap[nt][0]  = g_A[p];
        Ap[nt][1]  = g_A[p + 1];
    }

    float* stage = (float*)smem;

#pragma unroll
    for (int half = 0; half < 2; half++) {
        if ((wcol >> 2) == half) {
            int prow0 = (wcol & 3) * 32;
#pragma unroll
            for (int mt = 0; mt < 4; mt++)
#pragma unroll
                for (int nt = 0; nt < 4; nt++)
#pragma unroll
                    for (int v = 0; v < 4; v++) {
                        float dot = acc[mt][nt][v];
                        float hxb = (v & 2) ? hx1[mt] : hx0[mt];
                        float tt = (dot - hxb) * g2l[nt][v & 1];
                        float tr = tt + 12582912.f;
                        float fn = tr - 12582912.f;
                        float f  = tt - fn;
                        float pl = 1.3333558146e-3f;
                        pl = fmaf(pl, f, 9.6181291076e-3f);
                        pl = fmaf(pl, f, 5.5504108664e-2f);
                        pl = fmaf(pl, f, 2.4022650696e-1f);
                        pl = fmaf(pl, f, 6.9314718056e-1f);
                        pl = fmaf(pl, f, 1.0f);
                        int ei = __float_as_int(tr) << 23;
                        float ex = __int_as_float(__float_as_int(pl) + ei) * Ap[nt][v & 1];
                        int pr = prow0 + nt * 8 + (lane & 3) * 2 + (v & 1);
                        int bc = wrow * 64 + mt * 16 + (lane >> 2) + ((v >> 1) * 8);
                        stage[pr * STAGE_PITCH + bc] = ex;
                    }
        }
        __syncthreads();
#pragma unroll
        for (int i = 0; i < 8; i++) {
            int idx = t + i * 512;
            int row = idx >> 5;
            int c4  = idx & 31;
            float4 val = *(const float4*)(stage + row * STAGE_PITCH + c4 * 4);
            *(float4*)(&g_s[(size_t)(p0 + half * 128 + row) * BN + b0 + c4 * 4]) = val;
        }
        __syncthreads();
    }
}

// ---------------------------------------------------------------------------
// Scan segments: PURE PRODUCTS. T[c] = prod_k (U[k][c]*s + 1 - s), D = prod(1-s)
// (identity: mc + mn evolves multiplicatively; mc = T - D at the end)
// ---------------------------------------------------------------------------
__global__ void __launch_bounds__(256) scan_seg_kernel() {
    __shared__ __align__(16) float Us[SEGL][CN];
    const int seg = blockIdx.y;
    const int k0  = seg * SEGL;
    for (int i = threadIdx.x; i < SEGL * CN; i += 256)
        ((float*)Us)[i] = g_U[k0 * CN + i];
    __syncthreads();

    const int b = blockIdx.x * 256 + threadIdx.x;

    uint64_t T2[10];
    const uint64_t ONE2 = 0x3F8000003F800000ULL;
#pragma unroll
    for (int i = 0; i < 10; i++) T2[i] = ONE2;
    float D = 1.f;

    float cur[8], nxt[8];
#pragma unroll
    for (int i = 0; i < 8; i++) cur[i] = g_s[(size_t)(k0 + i) * BN + b];

    for (int kk = 0; kk < SEGL; kk += 8) {
        if (kk + 8 < SEGL) {
#pragma unroll
            for (int i = 0; i < 8; i++) nxt[i] = g_s[(size_t)(k0 + kk + 8 + i) * BN + b];
        }
#pragma unroll
        for (int i = 0; i < 8; i++) {
            float sk  = cur[i];
            float mn1 = 1.f - sk;
            uint64_t ss2 = pack2(sk);
            uint64_t mn2 = pack2(mn1);
            const ulonglong2* u2 = (const ulonglong2*)(&Us[kk + i][0]);
#pragma unroll
            for (int j = 0; j < 5; j++) {
                ulonglong2 up = u2[j];
                T2[j * 2 + 0] = mul2(T2[j * 2 + 0], fma2(up.x, ss2, mn2));
                T2[j * 2 + 1] = mul2(T2[j * 2 + 1], fma2(up.y, ss2, mn2));
            }
            D *= mn1;
        }
#pragma unroll
        for (int i = 0; i < 8; i++) cur[i] = nxt[i];
    }

#pragma unroll
    for (int i = 0; i < 10; i++) {
        float lo, hi;
        unpack2(lo, hi, T2[i]);
        g_segT[seg][i * 2 + 0][b] = lo;
        g_segT[seg][i * 2 + 1][b] = hi;
    }
    g_segD[seg][b] = D;
}

// ---------------------------------------------------------------------------
// Combine: multiply segment partials, mc = T - D, normalize.
// ---------------------------------------------------------------------------
__global__ void __launch_bounds__(256) combine_kernel(float* __restrict__ out) {
    const int gt = blockIdx.x * 256 + threadIdx.x;
    const int b  = gt >> 2;
    const int cg = gt & 3;

    float T[5], D = 1.f;
#pragma unroll
    for (int j = 0; j < 5; j++) T[j] = 1.f;

#pragma unroll
    for (int s = 0; s < NSEG; s++) {
#pragma unroll
        for (int j = 0; j < 5; j++) T[j] *= g_segT[s][cg * 5 + j][b];
        D *= g_segD[s][b];
    }

    float Ts = 0.f;
#pragma unroll
    for (int j = 0; j < 5; j++) Ts += T[j];
    Ts += __shfl_xor_sync(0xffffffffu, Ts, 1);
    Ts += __shfl_xor_sync(0xffffffffu, Ts, 2);
    float K = Ts - 19.f * D;
    float r = 1.f / K;

#pragma unroll
    for (int j = 0; j < 5; j++) out[b * (CN + 1) + cg * 5 + j] = (T[j] - D) * r;
    if (cg == 3) out[b * (CN + 1) + CN] = D * r;
}

// ---------------------------------------------------------------------------
extern "C" void kernel_launch(void* const* d_in, const int* in_sizes, int n_in,
                              void* d_out, int out_size) {
    const float* X     = (const float*)d_in[0];
    const float* W     = (const float*)d_in[1];
    const float* BETA  = (const float*)d_in[2];
    const float* alpha = (const float*)d_in[3];
    const float* gamma = (const float*)d_in[4];
    float* out = (float*)d_out;

    cudaFuncSetAttribute(gemm_hmma_kernel,
                         cudaFuncAttributeMaxDynamicSharedMemorySize, SMEM_TOTAL);

    prep_proto_kernel<<<PN, 32>>>(W, BETA, alpha, gamma);
    prep_x_kernel<<<BN / 8, 256>>>(X);

    dim3 ggrid(BN / 128, PN / 256);
    gemm_hmma_kernel<<<ggrid, 512, SMEM_TOTAL>>>();

    dim3 sgrid(BN / 256, NSEG);
    scan_seg_kernel<<<sgrid, 256>>>();

    combine_kernel<<<BN * 4 / 256, 256>>>(out);
}